// round 15
// baseline (speedup 1.0000x reference)
#include <cuda_runtime.h>

#define N_ROWS  262144
#define NBINS   50
#define DCOL    512
#define D2      256             // float2 columns
#define NBLK    256             // sort blocks (1024 rows each)
#define ROWS_PB 1024
#define SCH     16              // chunks per bin
#define NACC    (NBINS * SCH)   // 800 CTAs, all co-resident (<= 888 at 6/SM)

// -------- device scratch --------
__device__ int      g_bhist[NBLK][NBINS];   // per-block label histograms
__device__ int      g_off[NBINS + 1];       // bin offsets
__device__ int      g_cnt[NBINS];           // bin totals
__device__ int      g_sorted[N_ROWS];       // row indices sorted by bin (stable)
__device__ float4   g_bpart[NACC][D2];      // per-CTA partials {s0,q0,s1,q1}
__device__ volatile unsigned g_bar[3];      // phase barriers (zero-init, self-resetting)
__device__ unsigned g_done;

__device__ __forceinline__ int clampbin(int v) {
    return v < 0 ? 0 : (v >= NBINS ? NBINS - 1 : v);
}

// arrive with RED (atomicAdd), poll with plain volatile LOADS (no RMW contention)
__device__ __forceinline__ void grid_barrier(int id) {
    __syncthreads();
    if (threadIdx.x == 0) {
        __threadfence();                         // release: publish phase writes
        atomicAdd((unsigned*)&g_bar[id], 1u);
        while (g_bar[id] < (unsigned)NACC) __nanosleep(256);
        __threadfence();                         // acquire: see peers' writes
    }
    __syncthreads();
}

__global__ void __launch_bounds__(256, 6) mega_kernel(const float* __restrict__ feats,
                                                      const int*   __restrict__ labels,
                                                      const float* __restrict__ rmean,
                                                      const float* __restrict__ rvar,
                                                      const float* __restrict__ nst,
                                                      const float* __restrict__ kw,
                                                      float*       __restrict__ out) {
    const int blk = blockIdx.x;
    const int tid = threadIdx.x;

    // ---------------- Phase A: per-block label histograms (blocks 0..255) --------
    if (blk < NBLK) {
        __shared__ int h[NBINS];
        if (tid < NBINS) h[tid] = 0;
        __syncthreads();
        #pragma unroll
        for (int k = 0; k < 4; k++)
            atomicAdd(&h[clampbin(labels[blk * ROWS_PB + k * 256 + tid])], 1);
        __syncthreads();
        if (tid < NBINS) g_bhist[blk][tid] = h[tid];
    }
    grid_barrier(0);

    // ---------------- Phase B: inline scan + stable scatter (blocks 0..255) ------
    if (blk < NBLK) {
        __shared__ int stot[NBINS];
        __shared__ int sgb [NBINS];
        __shared__ int soff[NBINS + 1];
        __shared__ int cnt [NBINS];

        if (tid < NBINS) {
            int run = 0, gb = 0;
            #pragma unroll 16
            for (int k = 0; k < NBLK; k++) {
                int hh = g_bhist[k][tid];
                if (k == blk) gb = run;
                run += hh;
            }
            stot[tid] = run;
            sgb[tid]  = gb;
        }
        __syncthreads();
        if (tid == 0) {
            int off = 0;
            #pragma unroll
            for (int b = 0; b < NBINS; b++) { soff[b] = off; off += stot[b]; }
            soff[NBINS] = off;
        }
        __syncthreads();
        if (tid < NBINS) {
            cnt[tid] = soff[tid] + sgb[tid];
            if (blk == 0) {
                g_off[tid] = soff[tid];
                g_cnt[tid] = stot[tid];
                if (tid == 0) g_off[NBINS] = soff[NBINS];
            }
        }
        __syncthreads();

        if (tid < 32) {
            const int lane = tid;
            for (int t = 0; t < ROWS_PB / 32; t++) {
                const int r   = blk * ROWS_PB + t * 32 + lane;
                const int lab = clampbin(labels[r]);
                unsigned mask = __match_any_sync(0xFFFFFFFFu, lab);
                const int leader = __ffs(mask) - 1;
                const int rank   = __popc(mask & ((1u << lane) - 1u));
                int base = 0;
                if (lane == leader) {
                    base = cnt[lab];
                    cnt[lab] = base + __popc(mask);
                }
                base = __shfl_sync(0xFFFFFFFFu, base, leader);
                g_sorted[base + rank] = r;
                __syncwarp();
            }
        }
    }
    grid_barrier(1);

    // ---------------- Phase C: register-only accumulation (all 800 blocks) -------
    {
        const int b   = blk / SCH;
        const int j   = blk % SCH;
        const int o0  = g_off[b];
        const int len = g_off[b + 1] - o0;
        const int p0  = o0 + (int)((long long)len * j / SCH);
        const int p1  = o0 + (int)((long long)len * (j + 1) / SCH);

        const float2* __restrict__ f2 = (const float2*)feats;
        float s0 = 0.f, q0 = 0.f, s1 = 0.f, q1 = 0.f;

        int p = p0;
        int idx[8];
        const int nfull = (p1 - p0) / 8;
        if (nfull > 0) {
            #pragma unroll
            for (int u = 0; u < 8; u++) idx[u] = g_sorted[p + u];
        }
        for (int it = 0; it < nfull; it++) {
            float2 v[8];
            #pragma unroll
            for (int u = 0; u < 8; u++) v[u] = f2[(size_t)idx[u] * D2 + tid];

            if (it + 1 < nfull) {
                #pragma unroll
                for (int u = 0; u < 8; u++) idx[u] = g_sorted[p + 8 + u];
            }

            #pragma unroll
            for (int u = 0; u < 8; u++) {
                s0 += v[u].x; q0 = fmaf(v[u].x, v[u].x, q0);
                s1 += v[u].y; q1 = fmaf(v[u].y, v[u].y, q1);
            }
            p += 8;
        }
        for (; p < p1; p++) {
            float2 v = f2[(size_t)g_sorted[p] * D2 + tid];
            s0 += v.x; q0 = fmaf(v.x, v.x, q0);
            s1 += v.y; q1 = fmaf(v.y, v.y, q1);
        }
        g_bpart[blk][tid] = make_float4(s0, q0, s1, q1);
    }
    grid_barrier(2);

    // ---------------- Phase D: finalize + EMA + smooth (blocks 0..399) ----------
    if (blk < NBINS * 8) {
        __shared__ float4 sred[5][32];      // {nm0, nm1, nv0, nv1}
        const int b    = blk >> 3;          // bin
        const int cg   = blk & 7;           // column group (32 float4 cols)
        const int w    = tid >> 5;          // 0..7 (windows 0..4 active)
        const int cl   = tid & 31;
        const int col4 = cg * 32 + cl;      // global float4 col 0..255

        if (w < 5) {
            int m = b + w - 2;
            if (m < 0)      m = -m;                   // reflect101 left
            if (m >= NBINS) m = 2 * (NBINS - 1) - m;  // reflect101 right

            float4 acc = make_float4(0.f, 0.f, 0.f, 0.f);
            #pragma unroll
            for (int j = 0; j < SCH; j++) {
                float4 p = g_bpart[m * SCH + j][col4];
                acc.x += p.x; acc.y += p.y; acc.z += p.z; acc.w += p.w;
            }

            const float cnt    = (float)g_cnt[m];
            const float safe_n = fmaxf(cnt, 1.f);
            const float dn     = fmaxf(cnt - 1.f, 1.f);
            const float mm0 = acc.x / safe_n;
            const float vv0 = (acc.y - safe_n * mm0 * mm0) / dn;
            const float mm1 = acc.z / safe_n;
            const float vv1 = (acc.w - safe_n * mm1 * mm1) / dn;

            const int c0 = m * DCOL + 2 * col4;
            const float rm0 = rmean[c0], rm1 = rmean[c0 + 1];
            const float rv0 = rvar[c0],  rv1 = rvar[c0 + 1];
            const bool present = cnt > 0.f;
            const float f = 0.9f, g1 = 0.1f;

            const float nm0 = present ? g1 * mm0 + f * rm0 : rm0;
            const float nm1 = present ? g1 * mm1 + f * rm1 : rm1;
            const float nv0 = present ? g1 * vv0 + f * rv0 : rv0;
            const float nv1 = present ? g1 * vv1 + f * rv1 : rv1;

            if (w == 2) {   // m == b: this bin's new_mean / new_var
                ((float2*)out)[c0 / 2]                  = make_float2(nm0, nm1);
                ((float2*)(out + NBINS * DCOL))[c0 / 2] = make_float2(nv0, nv1);
            }
            sred[w][cl] = make_float4(nm0, nm1, nv0, nv1);
        }
        __syncthreads();

        if (w == 0) {
            const float wk[5] = {kw[0], kw[1], kw[2], kw[3], kw[4]};
            float sm0 = 0.f, sm1 = 0.f, sv0 = 0.f, sv1 = 0.f;
            #pragma unroll
            for (int k = 0; k < 5; k++) {
                float4 r = sred[k][cl];
                sm0 = fmaf(wk[k], r.x, sm0); sm1 = fmaf(wk[k], r.y, sm1);
                sv0 = fmaf(wk[k], r.z, sv0); sv1 = fmaf(wk[k], r.w, sv1);
            }
            const int base = 2 * NBINS * DCOL + NBINS;    // 51250
            const int o0   = b * DCOL + 2 * col4;
            ((float2*)(out + base))[o0 / 2]                = make_float2(sm0, sm1);
            ((float2*)(out + base + NBINS * DCOL))[o0 / 2] = make_float2(sv0, sv1);
        }
    }
    if (blk == 0 && tid < NBINS)
        out[2 * NBINS * DCOL + tid] = nst[tid] + (float)g_cnt[tid];   // new_num

    // ---------------- epilogue: last block resets barriers for next replay -------
    __syncthreads();
    if (tid == 0) {
        __threadfence();
        unsigned a = atomicAdd(&g_done, 1u);
        if (a == (unsigned)NACC - 1u) {
            g_bar[0] = 0u; g_bar[1] = 0u; g_bar[2] = 0u; g_done = 0u;
            __threadfence();
        }
    }
}

// -------- launch --------
extern "C" void kernel_launch(void* const* d_in, const int* in_sizes, int n_in,
                              void* d_out, int out_size) {
    const float* feats  = (const float*)d_in[0];
    const int*   labels = (const int*)d_in[1];
    const float* rmean  = (const float*)d_in[2];
    const float* rvar   = (const float*)d_in[3];
    const float* nst    = (const float*)d_in[4];
    const float* kw     = (const float*)d_in[5];
    float*       out    = (float*)d_out;

    mega_kernel<<<NACC, 256>>>(feats, labels, rmean, rvar, nst, kw, out);
}

// round 16
// speedup vs baseline: 1.1941x; 1.1941x over previous
#include <cuda_runtime.h>

#define N_ROWS  262144
#define NBINS   50
#define DCOL    512
#define D2      256             // float2 columns
#define NBLK    256             // sort blocks (1024 rows each)
#define ROWS_PB 1024
#define SCH     16              // chunks per bin
#define NACC    (NBINS * SCH)   // 800 accum CTAs
#define CG      4               // finsmooth column groups (64 float4 cols each)

// -------- device scratch --------
__device__ int    g_bhist[NBLK][NBINS];    // per-block label histograms
__device__ int    g_off[NBINS + 1];        // bin offsets (written by scatter blk 0)
__device__ int    g_cnt[NBINS];            // bin totals   (written by scatter blk 0)
__device__ int    g_sorted[N_ROWS];        // row indices sorted by bin (stable)
__device__ float4 g_bpart[NACC][D2];       // per-CTA partials {s0,q0,s1,q1}

__device__ __forceinline__ int clampbin(int v) {
    return v < 0 ? 0 : (v >= NBINS ? NBINS - 1 : v);
}

// -------- K1: per-block label histograms --------
__global__ void hist_kernel(const int* __restrict__ labels) {
    __shared__ int h[NBINS];
    const int tid = threadIdx.x, blk = blockIdx.x;
    if (tid < NBINS) h[tid] = 0;
    __syncthreads();
    #pragma unroll
    for (int k = 0; k < 4; k++)
        atomicAdd(&h[clampbin(labels[blk * ROWS_PB + k * 256 + tid])], 1);
    __syncthreads();
    if (tid < NBINS) g_bhist[blk][tid] = h[tid];
}

// -------- K2: scatter with inline scan (every block recomputes the prefix) --------
__global__ void __launch_bounds__(64) scatter_kernel(const int* __restrict__ labels) {
    __shared__ int stot[NBINS];   // bin totals
    __shared__ int sgb [NBINS];   // this block's per-bin exclusive base
    __shared__ int soff[NBINS + 1];
    __shared__ int cnt [NBINS];   // running write cursor
    const int tid = threadIdx.x, blk = blockIdx.x;

    if (tid < NBINS) {
        int run = 0, gb = 0;
        #pragma unroll 16
        for (int k = 0; k < NBLK; k++) {
            int h = g_bhist[k][tid];
            if (k == blk) gb = run;
            run += h;
        }
        stot[tid] = run;
        sgb[tid]  = gb;
    }
    __syncthreads();
    if (tid == 0) {
        int off = 0;
        #pragma unroll
        for (int b = 0; b < NBINS; b++) { soff[b] = off; off += stot[b]; }
        soff[NBINS] = off;
    }
    __syncthreads();
    if (tid < NBINS) {
        cnt[tid] = soff[tid] + sgb[tid];
        if (blk == 0) {
            g_off[tid] = soff[tid];
            g_cnt[tid] = stot[tid];
            if (tid == 0) g_off[NBINS] = soff[NBINS];
        }
    }
    __syncthreads();

    if (tid < 32) {
        const int lane = tid;
        for (int t = 0; t < ROWS_PB / 32; t++) {
            const int r   = blk * ROWS_PB + t * 32 + lane;
            const int lab = clampbin(labels[r]);
            unsigned mask = __match_any_sync(0xFFFFFFFFu, lab);
            const int leader = __ffs(mask) - 1;
            const int rank   = __popc(mask & ((1u << lane) - 1u));
            int base = 0;
            if (lane == leader) {
                base = cnt[lab];
                cnt[lab] = base + __popc(mask);
            }
            base = __shfl_sync(0xFFFFFFFFu, base, leader);
            g_sorted[base + rank] = r;
            __syncwarp();
        }
    }
}

// -------- K3: register-only accumulation, one bin per CTA, idx-ahead prefetch ----
__global__ void __launch_bounds__(256, 6) accum_kernel(const float* __restrict__ feats) {
    const int b   = blockIdx.x / SCH;
    const int j   = blockIdx.x % SCH;
    const int o0  = g_off[b];
    const int len = g_off[b + 1] - o0;
    const int p0  = o0 + (int)((long long)len * j / SCH);
    const int p1  = o0 + (int)((long long)len * (j + 1) / SCH);
    const int tid = threadIdx.x;

    const float2* __restrict__ f2 = (const float2*)feats;
    float s0 = 0.f, q0 = 0.f, s1 = 0.f, q1 = 0.f;

    int p = p0;
    int idx[8];
    const int nfull = (p1 - p0) / 8;
    if (nfull > 0) {
        #pragma unroll
        for (int u = 0; u < 8; u++) idx[u] = g_sorted[p + u];
    }
    for (int it = 0; it < nfull; it++) {
        float2 v[8];
        #pragma unroll
        for (int u = 0; u < 8; u++) v[u] = f2[(size_t)idx[u] * D2 + tid];

        if (it + 1 < nfull) {
            #pragma unroll
            for (int u = 0; u < 8; u++) idx[u] = g_sorted[p + 8 + u];
        }

        #pragma unroll
        for (int u = 0; u < 8; u++) {
            s0 += v[u].x; q0 = fmaf(v[u].x, v[u].x, q0);
            s1 += v[u].y; q1 = fmaf(v[u].y, v[u].y, q1);
        }
        p += 8;
    }
    for (; p < p1; p++) {
        float2 v = f2[(size_t)g_sorted[p] * D2 + tid];
        s0 += v.x; q0 = fmaf(v.x, v.x, q0);
        s1 += v.y; q1 = fmaf(v.y, v.y, q1);
    }
    g_bpart[blockIdx.x][tid] = make_float4(s0, q0, s1, q1);
}

// -------- K4: fused finalize + smooth, parallel windows --------
// grid = 50 bins x CG colgroups; block = 320 = 5 windows x 64 cols
__global__ void __launch_bounds__(320) finsmooth_kernel(const float* __restrict__ rmean,
                                                        const float* __restrict__ rvar,
                                                        const float* __restrict__ nst,
                                                        const float* __restrict__ kw,
                                                        float* __restrict__ out) {
    __shared__ float4 sred[5][64];          // {nm0, nm1, nv0, nv1} per window/col

    const int b    = blockIdx.x / CG;       // bin
    const int cg   = blockIdx.x % CG;       // column group
    const int tid  = threadIdx.x;
    const int w    = tid / 64;              // window 0..4
    const int cl   = tid % 64;              // local float4 col
    const int col4 = cg * 64 + cl;          // global float4 col 0..255

    if (blockIdx.x == 0 && tid < NBINS)
        out[2 * NBINS * DCOL + tid] = nst[tid] + (float)g_cnt[tid];   // new_num

    int m = b + w - 2;
    if (m < 0)      m = -m;                   // reflect101 left
    if (m >= NBINS) m = 2 * (NBINS - 1) - m;  // reflect101 right

    // reduce 16 chunk partials for (window bin m, col4)
    float4 acc = make_float4(0.f, 0.f, 0.f, 0.f);
    #pragma unroll
    for (int j = 0; j < SCH; j++) {
        float4 p = g_bpart[m * SCH + j][col4];
        acc.x += p.x; acc.y += p.y; acc.z += p.z; acc.w += p.w;
    }

    const float cnt    = (float)g_cnt[m];
    const float safe_n = fmaxf(cnt, 1.f);
    const float dn     = fmaxf(cnt - 1.f, 1.f);
    const float mm0 = acc.x / safe_n;
    const float vv0 = (acc.y - safe_n * mm0 * mm0) / dn;
    const float mm1 = acc.z / safe_n;
    const float vv1 = (acc.w - safe_n * mm1 * mm1) / dn;

    const int c0 = m * DCOL + 2 * col4;
    const float rm0 = rmean[c0], rm1 = rmean[c0 + 1];
    const float rv0 = rvar[c0],  rv1 = rvar[c0 + 1];
    const bool present = cnt > 0.f;
    const float f = 0.9f, g1 = 0.1f;

    const float nm0 = present ? g1 * mm0 + f * rm0 : rm0;
    const float nm1 = present ? g1 * mm1 + f * rm1 : rm1;
    const float nv0 = present ? g1 * vv0 + f * rv0 : rv0;
    const float nv1 = present ? g1 * vv1 + f * rv1 : rv1;

    if (w == 2) {   // m == b: write this bin's new_mean / new_var
        ((float2*)out)[c0 / 2]                  = make_float2(nm0, nm1);
        ((float2*)(out + NBINS * DCOL))[c0 / 2] = make_float2(nv0, nv1);
    }

    sred[w][cl] = make_float4(nm0, nm1, nv0, nv1);
    __syncthreads();

    if (w == 0) {
        const float wk[5] = {kw[0], kw[1], kw[2], kw[3], kw[4]};
        float sm0 = 0.f, sm1 = 0.f, sv0 = 0.f, sv1 = 0.f;
        #pragma unroll
        for (int k = 0; k < 5; k++) {
            float4 r = sred[k][cl];
            sm0 = fmaf(wk[k], r.x, sm0); sm1 = fmaf(wk[k], r.y, sm1);
            sv0 = fmaf(wk[k], r.z, sv0); sv1 = fmaf(wk[k], r.w, sv1);
        }
        const int base = 2 * NBINS * DCOL + NBINS;    // 51250
        const int o0   = b * DCOL + 2 * col4;
        ((float2*)(out + base))[o0 / 2]                = make_float2(sm0, sm1); // smoothed_mean
        ((float2*)(out + base + NBINS * DCOL))[o0 / 2] = make_float2(sv0, sv1); // smoothed_var
    }
}

// -------- launch --------
extern "C" void kernel_launch(void* const* d_in, const int* in_sizes, int n_in,
                              void* d_out, int out_size) {
    const float* feats  = (const float*)d_in[0];
    const int*   labels = (const int*)d_in[1];
    const float* rmean  = (const float*)d_in[2];
    const float* rvar   = (const float*)d_in[3];
    const float* nst    = (const float*)d_in[4];
    const float* kw     = (const float*)d_in[5];
    float*       out    = (float*)d_out;

    hist_kernel<<<NBLK, 256>>>(labels);
    scatter_kernel<<<NBLK, 64>>>(labels);
    accum_kernel<<<NACC, 256>>>(feats);
    finsmooth_kernel<<<NBINS * CG, 320>>>(rmean, rvar, nst, kw, out);
}